// round 2
// baseline (speedup 1.0000x reference)
#include <cuda_runtime.h>
#include <math.h>

#define BATCH 2
#define H0 480
#define W0 640
#define NP0 (H0*W0)

// ---------------- scratch (device globals; no allocation allowed) ----------------
__device__ float g_x   [BATCH*6 *NP0];   // per-scale concat input: I(3), DLs, MLs, Es
__device__ float g_f0  [BATCH*65*NP0];   // feat buffer (65 ch: feat + D/DMAX for curv)
__device__ float g_f1  [BATCH*64*NP0];   // intermediate feat
__device__ float g_A   [BATCH*24*NP0];   // affinities (normalized in place)
__device__ float g_gate[BATCH*3 *NP0];
__device__ float g_curv[BATCH*3 *NP0];
__device__ float g_csk [BATCH*9 *NP0];   // center(3), sigma(3), kappa(3)
__device__ float g_D   [BATCH*NP0];
__device__ float g_D2  [BATCH*NP0];
__device__ float g_Dp  [BATCH*NP0];      // previous-scale result

__device__ float g_wT0[6 *9*64];
__device__ float g_wT1[64*9*64];
__device__ float g_wT2[64*9*64];
__device__ float g_wTa[64*9*24];
__device__ float g_wTg[64*9*3];
__device__ float g_wTc[65*9*3];

// ---------------- weight transpose: OIHW -> [ci][tap][co] ----------------
__global__ void transpose_w_kernel(const float* __restrict__ w, float* __restrict__ wT,
                                   int Cout, int Cin) {
    int i = blockIdx.x*blockDim.x + threadIdx.x;
    int total = Cout*Cin*9;
    if (i >= total) return;
    int co = i / (Cin*9);
    int r  = i % (Cin*9);
    int ci = r / 9;
    int t  = r % 9;
    wT[(ci*9 + t)*Cout + co] = w[i];
}

// ---------------- antialiased triangle-kernel downsample weights (jax.image.resize) ----------------
template<int F>
__device__ __forceinline__ void down_weights(int i, int n, int& j0, float* w, float& ws) {
    // sample_f = (i+0.5)*F - 0.5 ; kernel width scaled by F (antialias); renormalize in-range taps
    float c = (float)(F*i) + 0.5f*(float)F - 0.5f;
    j0 = (int)ceilf(c - (float)F);
    ws = 0.f;
#pragma unroll
    for (int t = 0; t < 2*F; t++) {
        int j = j0 + t;
        float wv = (j >= 0 && j < n) ? (1.f - fabsf((float)j - c) * (1.f/(float)F)) : 0.f;
        w[t] = wv; ws += wv;
    }
}

// ---------------- per-scale prep: resize I/E, down_sparse DL/ML, write g_x (+ D at first scale) ----------------
template<int S, bool FIRST>
__global__ void prep_kernel(const float* __restrict__ I, const float* __restrict__ DL,
                            const float* __restrict__ ML, const float* __restrict__ E,
                            int Hs, int Ws) {
    int NPs = Hs*Ws;
    int gid = blockIdx.x*blockDim.x + threadIdx.x;
    if (gid >= BATCH*NPs) return;
    int b = gid / NPs, p = gid % NPs;
    int y = p / Ws, x = p % Ws;

    float iv0, iv1, iv2, ev;
    if (S == 1) {
        const float* Ib = I + (size_t)b*3*NP0;
        iv0 = Ib[p]; iv1 = Ib[NP0 + p]; iv2 = Ib[2*NP0 + p];
        ev  = E[(size_t)b*NP0 + p];
    } else {
        float wy[2*S], wx[2*S], wys, wxs;
        int jy0, jx0;
        down_weights<S>(y, H0, jy0, wy, wys);
        down_weights<S>(x, W0, jx0, wx, wxs);
        float a0=0.f, a1=0.f, a2=0.f, ae=0.f;
        const float* Ib = I + (size_t)b*3*NP0;
        const float* Eb = E + (size_t)b*NP0;
#pragma unroll
        for (int ty = 0; ty < 2*S; ty++) {
            int yy = jy0 + ty;
            if (yy < 0 || yy >= H0) continue;
            float wyv = wy[ty];
#pragma unroll
            for (int tx = 0; tx < 2*S; tx++) {
                int xx = jx0 + tx;
                if (xx < 0 || xx >= W0) continue;
                float wv = wyv * wx[tx];
                int q = yy*W0 + xx;
                a0 += wv*Ib[q];
                a1 += wv*Ib[NP0 + q];
                a2 += wv*Ib[2*NP0 + q];
                ae += wv*Eb[q];
            }
        }
        float inv = 1.f / (wys * wxs);
        iv0 = a0*inv; iv1 = a1*inv; iv2 = a2*inv; ev = ae*inv;
    }
    ev = fminf(fmaxf(ev, 0.f), 1.f);

    float dls, mls;
    if (S == 1) {
        mls = ML[(size_t)b*NP0 + p] > 0.f ? 1.f : 0.f;
        dls = DL[(size_t)b*NP0 + p];
    } else {
        float s = 0.f, c = 0.f;
        for (int dy = 0; dy < S; dy++)
            for (int dx = 0; dx < S; dx++) {
                int q = (y*S + dy)*W0 + (x*S + dx);
                float m = ML[(size_t)b*NP0 + q] > 0.f ? 1.f : 0.f;
                c += m;
                s += DL[(size_t)b*NP0 + q] * m;
            }
        mls = c > 0.f ? 1.f : 0.f;
        dls = c > 0.f ? s / (c + 1e-6f) : 0.f;
    }

    size_t xb = (size_t)b*6*NPs;
    g_x[xb + 0*(size_t)NPs + p] = iv0;
    g_x[xb + 1*(size_t)NPs + p] = iv1;
    g_x[xb + 2*(size_t)NPs + p] = iv2;
    g_x[xb + 3*(size_t)NPs + p] = dls;
    g_x[xb + 4*(size_t)NPs + p] = mls;
    g_x[xb + 5*(size_t)NPs + p] = ev;
    if (FIRST) g_D[(size_t)b*NPs + p] = fminf(ev*10.f, 10.f);
}

// ---------------- init D from previous scale (edge-aware blend of 2x-upsampled prev) ----------------
__global__ void init_d_kernel(int Hp, int Wp, int Hs, int Ws) {
    int NPs = Hs*Ws;
    int gid = blockIdx.x*blockDim.x + threadIdx.x;
    if (gid >= BATCH*NPs) return;
    int b = gid / NPs, p = gid % NPs;
    int y = p / Ws, x = p % Ws;

    const float* Eb = g_x + ((size_t)b*6 + 5)*NPs;
    float e = Eb[p];
    float gxv = (x > 0) ? e - Eb[p-1]  : 0.f;
    float gyv = (y > 0) ? e - Eb[p-Ws] : 0.f;
    float g = fminf(0.5f*(fabsf(gxv)+fabsf(gyv)), 1.f);
    float w = 0.7f * fminf(fmaxf(1.f - g*10.f, 0.f), 1.f);

    // half-pixel 2x upsample with boundary renorm (== jax.image.resize linear upsample)
    float cy = (y + 0.5f)*0.5f - 0.5f;
    float cx = (x + 0.5f)*0.5f - 0.5f;
    int y0 = (int)floorf(cy), x0 = (int)floorf(cx);
    float fy = cy - (float)y0, fx = cx - (float)x0;
    float wyv[2] = {1.f - fy, fy};
    float wxv[2] = {1.f - fx, fx};
    const float* Dpb = g_Dp + (size_t)b*Hp*Wp;
    float wsy = 0.f, wsx = 0.f;
#pragma unroll
    for (int a = 0; a < 2; a++) if (y0+a >= 0 && y0+a < Hp) wsy += wyv[a];
#pragma unroll
    for (int a = 0; a < 2; a++) if (x0+a >= 0 && x0+a < Wp) wsx += wxv[a];
    float acc = 0.f;
#pragma unroll
    for (int a = 0; a < 2; a++) {
        int yy = y0 + a;
        if (yy < 0 || yy >= Hp) continue;
#pragma unroll
        for (int c2 = 0; c2 < 2; c2++) {
            int xx = x0 + c2;
            if (xx < 0 || xx >= Wp) continue;
            acc += wyv[a]*wxv[c2]*Dpb[(size_t)yy*Wp + xx];
        }
    }
    float up = acc / (wsy * wsx);
    float P = fminf(e*10.f, 10.f);
    g_D[(size_t)b*NPs + p] = w*up + (1.f - w)*P;
}

// ---------------- direct 3x3 conv, SAME padding, NCHW. wT layout [ci][tap][co] ----------------
#define CTW 32
#define CTH 8
#define CI_CHUNK 8

template<int COUT, bool RELU>
__global__ void __launch_bounds__(256, 2) conv3x3_kernel(
    const float* __restrict__ in, const float* __restrict__ wT,
    const float* __restrict__ bias, float* __restrict__ out,
    int Cin, int inCtot, int outCtot, int Hs, int Ws) {
    __shared__ float s_in[CI_CHUNK][CTH+2][CTW+2];
    __shared__ float s_w[CI_CHUNK*9*COUT];

    int NPs = Hs*Ws;
    int b  = blockIdx.z;
    int x0 = blockIdx.x*CTW, y0 = blockIdx.y*CTH;
    int tx = threadIdx.x, ty = threadIdx.y;
    int tid = ty*CTW + tx;
    int x = x0 + tx, y = y0 + ty;

    float acc[COUT];
#pragma unroll
    for (int co = 0; co < COUT; co++) acc[co] = bias[co];

    for (int ci0 = 0; ci0 < Cin; ci0 += CI_CHUNK) {
        int cc = min(CI_CHUNK, Cin - ci0);
        int nW = cc*9*COUT;
        const float* wsrc = wT + (size_t)ci0*9*COUT;
        for (int i = tid; i < nW; i += CTW*CTH) s_w[i] = wsrc[i];
        int nI = cc*(CTH+2)*(CTW+2);
        for (int i = tid; i < nI; i += CTW*CTH) {
            int c = i / ((CTH+2)*(CTW+2));
            int r = i % ((CTH+2)*(CTW+2));
            int iy = r / (CTW+2), ix = r % (CTW+2);
            int gy = y0 + iy - 1, gx = x0 + ix - 1;
            float v = 0.f;
            if (gy >= 0 && gy < Hs && gx >= 0 && gx < Ws)
                v = in[((size_t)b*inCtot + ci0 + c)*NPs + (size_t)gy*Ws + gx];
            s_in[c][iy][ix] = v;
        }
        __syncthreads();
        for (int ci = 0; ci < cc; ci++) {
            float v[9];
#pragma unroll
            for (int dy = 0; dy < 3; dy++)
#pragma unroll
                for (int dx = 0; dx < 3; dx++)
                    v[dy*3+dx] = s_in[ci][ty+dy][tx+dx];
            const float* wp = &s_w[ci*9*COUT];
#pragma unroll
            for (int t = 0; t < 9; t++) {
                float vv = v[t];
#pragma unroll
                for (int co = 0; co < COUT; co++)
                    acc[co] = fmaf(vv, wp[t*COUT + co], acc[co]);
            }
        }
        __syncthreads();
    }

    if (x < Ws && y < Hs) {
        size_t o = (size_t)b*outCtot*NPs + (size_t)y*Ws + x;
#pragma unroll
        for (int co = 0; co < COUT; co++) {
            float r = acc[co];
            if (RELU) r = fmaxf(r, 0.f);
            out[o + (size_t)co*NPs] = r;
        }
    }
}

// ---------------- write D/DMAX into channel 64 of g_f0 (curv conv input) ----------------
__global__ void dnorm_kernel(int Hs, int Ws) {
    int NPs = Hs*Ws;
    int gid = blockIdx.x*blockDim.x + threadIdx.x;
    if (gid >= BATCH*NPs) return;
    int b = gid / NPs, p = gid % NPs;
    g_f0[((size_t)b*65 + 64)*NPs + p] = g_D[(size_t)b*NPs + p] * 0.1f;
}

// ---------------- head finalize: normalize A, center, softmax gate, kappa ----------------
__global__ void head_kernel(int NPs) {
    int gid = blockIdx.x*blockDim.x + threadIdx.x;
    if (gid >= BATCH*NPs) return;
    int b = gid / NPs, p = gid % NPs;
    size_t Ab = (size_t)b*24*NPs + p;
    size_t Cb = (size_t)b*9*NPs + p;
#pragma unroll
    for (int k = 0; k < 3; k++) {
        float a[8];
        float sab = 1e-6f;
#pragma unroll
        for (int j = 0; j < 8; j++) {
            a[j] = g_A[Ab + (size_t)(k*8+j)*NPs];
            sab += fabsf(a[j]);
        }
        float inv = 1.f / sab, sm = 0.f;
#pragma unroll
        for (int j = 0; j < 8; j++) {
            float an = a[j]*inv;
            g_A[Ab + (size_t)(k*8+j)*NPs] = an;
            sm += an;
        }
        g_csk[Cb + (size_t)k*NPs] = 1.f - sm;
    }
    size_t Gb = (size_t)b*3*NPs + p;
    float g0 = g_gate[Gb], g1 = g_gate[Gb + NPs], g2 = g_gate[Gb + 2*(size_t)NPs];
    float m = fmaxf(g0, fmaxf(g1, g2));
    float e0 = expf(g0 - m), e1 = expf(g1 - m), e2 = expf(g2 - m);
    float inv = 1.f / (e0 + e1 + e2);
    g_csk[Cb + 3*(size_t)NPs] = e0*inv;
    g_csk[Cb + 4*(size_t)NPs] = e1*inv;
    g_csk[Cb + 5*(size_t)NPs] = e2*inv;
#pragma unroll
    for (int k = 0; k < 3; k++) {
        float c = g_curv[Gb + (size_t)k*NPs];
        g_csk[Cb + (size_t)(6+k)*NPs] = 0.1f + 0.9f / (1.f + expf(-c));
    }
}

// ---------------- one propagation step ----------------
__global__ void prop_kernel(const float* __restrict__ Din, float* __restrict__ Dout,
                            int Hs, int Ws) {
    int NPs = Hs*Ws;
    int gid = blockIdx.x*blockDim.x + threadIdx.x;
    if (gid >= BATCH*NPs) return;
    int b = gid / NPs, p = gid % NPs;
    int y = p / Ws, x = p % Ws;
    const float* Db = Din + (size_t)b*NPs;
    float d = Db[p];
    size_t Ab = (size_t)b*24*NPs + p;
    size_t Cb = (size_t)b*9*NPs + p;
    const int offy[8] = {-1,-1,-1, 0, 0, 1, 1, 1};
    const int offx[8] = {-1, 0, 1,-1, 1,-1, 0, 1};
    const int dil[3]  = {1, 2, 4};
    float mix = 0.f;
#pragma unroll
    for (int k = 0; k < 3; k++) {
        float agg = g_csk[Cb + (size_t)k*NPs] * d;  // center_k * D
        int dd = dil[k];
#pragma unroll
        for (int j = 0; j < 8; j++) {
            int ny = y + offy[j]*dd, nx = x + offx[j]*dd;
            float nb = (ny >= 0 && ny < Hs && nx >= 0 && nx < Ws) ? Db[(size_t)ny*Ws + nx] : 0.f;
            agg += g_A[Ab + (size_t)(k*8+j)*NPs] * nb;
        }
        float sig = g_csk[Cb + (size_t)(3+k)*NPs];
        float kap = g_csk[Cb + (size_t)(6+k)*NPs];
        mix += sig * (d + kap*(agg - d));
    }
    size_t xb = (size_t)b*6*NPs + p;
    float dls = g_x[xb + 3*(size_t)NPs];
    float mls = g_x[xb + 4*(size_t)NPs];
    Dout[(size_t)b*NPs + p] = mls*(0.9f*dls + 0.1f*mix) + (1.f - mls)*mix;
}

// ---------------- host orchestration ----------------
extern "C" void kernel_launch(void* const* d_in, const int* in_sizes, int n_in,
                              void* d_out, int out_size) {
    (void)in_sizes; (void)n_in; (void)out_size;
    const float* I  = (const float*)d_in[0];
    const float* DL = (const float*)d_in[1];
    const float* ML = (const float*)d_in[2];
    const float* E  = (const float*)d_in[3];
    const float* w0 = (const float*)d_in[4];
    const float* b0 = (const float*)d_in[5];
    const float* w1 = (const float*)d_in[6];
    const float* b1 = (const float*)d_in[7];
    const float* w2 = (const float*)d_in[8];
    const float* b2 = (const float*)d_in[9];
    const float* wa = (const float*)d_in[10];
    const float* ba = (const float*)d_in[11];
    const float* wg = (const float*)d_in[12];
    const float* bg = (const float*)d_in[13];
    const float* wc = (const float*)d_in[14];
    const float* bc = (const float*)d_in[15];
    float* out = (float*)d_out;

    float *px, *pf0, *pf1, *pA, *pD, *pD2, *pDp;
    float *pgate, *pcurv;
    float *pwT0, *pwT1, *pwT2, *pwTa, *pwTg, *pwTc;
    cudaGetSymbolAddress((void**)&px,   g_x);
    cudaGetSymbolAddress((void**)&pf0,  g_f0);
    cudaGetSymbolAddress((void**)&pf1,  g_f1);
    cudaGetSymbolAddress((void**)&pA,   g_A);
    cudaGetSymbolAddress((void**)&pgate, g_gate);
    cudaGetSymbolAddress((void**)&pcurv, g_curv);
    cudaGetSymbolAddress((void**)&pD,   g_D);
    cudaGetSymbolAddress((void**)&pD2,  g_D2);
    cudaGetSymbolAddress((void**)&pDp,  g_Dp);
    cudaGetSymbolAddress((void**)&pwT0, g_wT0);
    cudaGetSymbolAddress((void**)&pwT1, g_wT1);
    cudaGetSymbolAddress((void**)&pwT2, g_wT2);
    cudaGetSymbolAddress((void**)&pwTa, g_wTa);
    cudaGetSymbolAddress((void**)&pwTg, g_wTg);
    cudaGetSymbolAddress((void**)&pwTc, g_wTc);

    // weight transposes (tiny)
    {
        int n;
        n = 64*6*9;  transpose_w_kernel<<<(n+255)/256, 256>>>(w0, pwT0, 64, 6);
        n = 64*64*9; transpose_w_kernel<<<(n+255)/256, 256>>>(w1, pwT1, 64, 64);
        n = 64*64*9; transpose_w_kernel<<<(n+255)/256, 256>>>(w2, pwT2, 64, 64);
        n = 24*64*9; transpose_w_kernel<<<(n+255)/256, 256>>>(wa, pwTa, 24, 64);
        n = 3*64*9;  transpose_w_kernel<<<(n+255)/256, 256>>>(wg, pwTg, 3, 64);
        n = 3*65*9;  transpose_w_kernel<<<(n+255)/256, 256>>>(wc, pwTc, 3, 65);
    }

    const int SC[3] = {4, 2, 1};
    int Hp = 0, Wp = 0;
    for (int si = 0; si < 3; si++) {
        int S = SC[si];
        int Hs = H0 / S, Ws = W0 / S;
        int NPs = Hs * Ws;
        int tot = BATCH * NPs;
        int thr = 256, blk = (tot + thr - 1) / thr;

        if (si == 0) {
            prep_kernel<4, true><<<blk, thr>>>(I, DL, ML, E, Hs, Ws);
        } else if (si == 1) {
            prep_kernel<2, false><<<blk, thr>>>(I, DL, ML, E, Hs, Ws);
            init_d_kernel<<<blk, thr>>>(Hp, Wp, Hs, Ws);
        } else {
            prep_kernel<1, false><<<blk, thr>>>(I, DL, ML, E, Hs, Ws);
            init_d_kernel<<<blk, thr>>>(Hp, Wp, Hs, Ws);
        }

        dim3 cb(CTW, CTH);
        dim3 cg((Ws + CTW - 1)/CTW, (Hs + CTH - 1)/CTH, BATCH);
        // enc0: g_x(6) -> g_f0 ; enc1: g_f0 -> g_f1 ; enc2: g_f1 -> g_f0 (feat)
        conv3x3_kernel<64, true ><<<cg, cb>>>(px,  pwT0, b0, pf0, 6,  6,  65, Hs, Ws);
        conv3x3_kernel<64, true ><<<cg, cb>>>(pf0, pwT1, b1, pf1, 64, 65, 64, Hs, Ws);
        conv3x3_kernel<64, true ><<<cg, cb>>>(pf1, pwT2, b2, pf0, 64, 64, 65, Hs, Ws);
        conv3x3_kernel<24, false><<<cg, cb>>>(pf0, pwTa, ba, pA,  64, 65, 24, Hs, Ws);
        conv3x3_kernel<3,  false><<<cg, cb>>>(pf0, pwTg, bg, pgate, 64, 65, 3, Hs, Ws);
        dnorm_kernel<<<blk, thr>>>(Hs, Ws);
        conv3x3_kernel<3,  false><<<cg, cb>>>(pf0, pwTc, bc, pcurv, 65, 65, 3, Hs, Ws);
        head_kernel<<<blk, thr>>>(NPs);

        float* Dc = pD;
        float* Dn = pD2;
        for (int st = 0; st < 6; st++) {
            prop_kernel<<<blk, thr>>>(Dc, Dn, Hs, Ws);
            float* t = Dc; Dc = Dn; Dn = t;
        }
        if (si < 2) {
            cudaMemcpyAsync(pDp, Dc, sizeof(float)*(size_t)BATCH*NPs, cudaMemcpyDeviceToDevice);
        } else {
            cudaMemcpyAsync(out, Dc, sizeof(float)*(size_t)BATCH*NPs, cudaMemcpyDeviceToDevice);
        }
        Hp = Hs; Wp = Ws;
    }
}

// round 3
// speedup vs baseline: 1.1332x; 1.1332x over previous
#include <cuda_runtime.h>
#include <math.h>

#define BATCH 2
#define H0 480
#define W0 640
#define NP0 (H0*W0)

// ---------------- scratch (device globals; no allocation allowed) ----------------
__device__ float g_x   [BATCH*6 *NP0];   // per-scale concat input: I(3), DLs, MLs, Es
__device__ float g_f0  [BATCH*65*NP0];   // feat buffer (65 ch: feat + D/DMAX for curv)
__device__ float g_f1  [BATCH*64*NP0];   // intermediate feat
__device__ float g_A   [BATCH*24*NP0];   // normalized affinities
__device__ float g_csk [BATCH*9 *NP0];   // center(3), sigma(3), kappa(3)
__device__ float g_D   [BATCH*NP0];
__device__ float g_D2  [BATCH*NP0];
__device__ float g_Dp  [BATCH*NP0];      // previous-scale result

__device__ float g_wT0 [6 *9*64];
__device__ float g_wT1 [64*9*64];
__device__ float g_wT2 [64*9*64];
__device__ float g_wTagc[65*9*32];       // fused aff(24)+gate(3)+curv(3)+pad(2)
__device__ float g_bagc[32];

// ---------------- f32x2 helpers (Blackwell packed fp32) ----------------
__device__ __forceinline__ void fma2(unsigned long long& d, unsigned long long a,
                                     unsigned long long b) {
    asm("fma.rn.f32x2 %0, %1, %2, %0;" : "+l"(d) : "l"(a), "l"(b));
}
__device__ __forceinline__ unsigned long long pack2(float lo, float hi) {
    unsigned long long r;
    asm("mov.b64 %0, {%1, %2};" : "=l"(r) : "f"(lo), "f"(hi));
    return r;
}
__device__ __forceinline__ void unpack2(unsigned long long v, float& lo, float& hi) {
    asm("mov.b64 {%0, %1}, %2;" : "=f"(lo), "=f"(hi) : "l"(v));
}

// ---------------- weight transpose: OIHW -> [ci][tap][co] ----------------
__global__ void transpose_w_kernel(const float* __restrict__ w, float* __restrict__ wT,
                                   int Cout, int Cin) {
    int i = blockIdx.x*blockDim.x + threadIdx.x;
    int total = Cout*Cin*9;
    if (i >= total) return;
    int co = i / (Cin*9);
    int r  = i % (Cin*9);
    int ci = r / 9;
    int t  = r % 9;
    wT[(ci*9 + t)*Cout + co] = w[i];
}

// ---------------- build fused aff/gate/curv weights [ci(65)][tap][co(32)] ----------------
__global__ void build_agc_kernel(const float* __restrict__ wa, const float* __restrict__ ba,
                                 const float* __restrict__ wg, const float* __restrict__ bg,
                                 const float* __restrict__ wc, const float* __restrict__ bc) {
    int i = blockIdx.x*blockDim.x + threadIdx.x;
    if (i < 32) {
        float bv = 0.f;
        if (i < 24) bv = ba[i];
        else if (i < 27) bv = bg[i-24];
        else if (i < 30) bv = bc[i-27];
        g_bagc[i] = bv;
    }
    int total = 65*9*32;
    if (i >= total) return;
    int co = i % 32;
    int t  = (i / 32) % 9;
    int ci = i / (32*9);
    float v = 0.f;
    if (co < 24)      { if (ci < 64) v = wa[(size_t)co*64*9 + ci*9 + t]; }
    else if (co < 27) { if (ci < 64) v = wg[(size_t)(co-24)*64*9 + ci*9 + t]; }
    else if (co < 30) { v = wc[(size_t)(co-27)*65*9 + ci*9 + t]; }
    g_wTagc[(ci*9 + t)*32 + co] = v;
}

// ---------------- antialiased triangle-kernel downsample weights (jax.image.resize) ----------------
template<int F>
__device__ __forceinline__ void down_weights(int i, int n, int& j0, float* w, float& ws) {
    float c = (float)(F*i) + 0.5f*(float)F - 0.5f;
    j0 = (int)ceilf(c - (float)F);
    ws = 0.f;
#pragma unroll
    for (int t = 0; t < 2*F; t++) {
        int j = j0 + t;
        float wv = (j >= 0 && j < n) ? (1.f - fabsf((float)j - c) * (1.f/(float)F)) : 0.f;
        w[t] = wv; ws += wv;
    }
}

// ---------------- per-scale prep ----------------
template<int S, bool FIRST>
__global__ void prep_kernel(const float* __restrict__ I, const float* __restrict__ DL,
                            const float* __restrict__ ML, const float* __restrict__ E,
                            int Hs, int Ws) {
    int NPs = Hs*Ws;
    int gid = blockIdx.x*blockDim.x + threadIdx.x;
    if (gid >= BATCH*NPs) return;
    int b = gid / NPs, p = gid % NPs;
    int y = p / Ws, x = p % Ws;

    float iv0, iv1, iv2, ev;
    if (S == 1) {
        const float* Ib = I + (size_t)b*3*NP0;
        iv0 = Ib[p]; iv1 = Ib[NP0 + p]; iv2 = Ib[2*NP0 + p];
        ev  = E[(size_t)b*NP0 + p];
    } else {
        float wy[2*S], wx[2*S], wys, wxs;
        int jy0, jx0;
        down_weights<S>(y, H0, jy0, wy, wys);
        down_weights<S>(x, W0, jx0, wx, wxs);
        float a0=0.f, a1=0.f, a2=0.f, ae=0.f;
        const float* Ib = I + (size_t)b*3*NP0;
        const float* Eb = E + (size_t)b*NP0;
#pragma unroll
        for (int ty = 0; ty < 2*S; ty++) {
            int yy = jy0 + ty;
            if (yy < 0 || yy >= H0) continue;
            float wyv = wy[ty];
#pragma unroll
            for (int tx = 0; tx < 2*S; tx++) {
                int xx = jx0 + tx;
                if (xx < 0 || xx >= W0) continue;
                float wv = wyv * wx[tx];
                int q = yy*W0 + xx;
                a0 += wv*Ib[q];
                a1 += wv*Ib[NP0 + q];
                a2 += wv*Ib[2*NP0 + q];
                ae += wv*Eb[q];
            }
        }
        float inv = 1.f / (wys * wxs);
        iv0 = a0*inv; iv1 = a1*inv; iv2 = a2*inv; ev = ae*inv;
    }
    ev = fminf(fmaxf(ev, 0.f), 1.f);

    float dls, mls;
    if (S == 1) {
        mls = ML[(size_t)b*NP0 + p] > 0.f ? 1.f : 0.f;
        dls = DL[(size_t)b*NP0 + p];
    } else {
        float s = 0.f, c = 0.f;
        for (int dy = 0; dy < S; dy++)
            for (int dx = 0; dx < S; dx++) {
                int q = (y*S + dy)*W0 + (x*S + dx);
                float m = ML[(size_t)b*NP0 + q] > 0.f ? 1.f : 0.f;
                c += m;
                s += DL[(size_t)b*NP0 + q] * m;
            }
        mls = c > 0.f ? 1.f : 0.f;
        dls = c > 0.f ? s / (c + 1e-6f) : 0.f;
    }

    size_t xb = (size_t)b*6*NPs;
    g_x[xb + 0*(size_t)NPs + p] = iv0;
    g_x[xb + 1*(size_t)NPs + p] = iv1;
    g_x[xb + 2*(size_t)NPs + p] = iv2;
    g_x[xb + 3*(size_t)NPs + p] = dls;
    g_x[xb + 4*(size_t)NPs + p] = mls;
    g_x[xb + 5*(size_t)NPs + p] = ev;
    if (FIRST) {
        float D = fminf(ev*10.f, 10.f);
        g_D[(size_t)b*NPs + p] = D;
        g_f0[((size_t)b*65 + 64)*NPs + p] = D * 0.1f;  // curv conv channel
    }
}

// ---------------- init D from previous scale (edge-aware blend of 2x-upsampled prev) ----------------
__global__ void init_d_kernel(int Hp, int Wp, int Hs, int Ws) {
    int NPs = Hs*Ws;
    int gid = blockIdx.x*blockDim.x + threadIdx.x;
    if (gid >= BATCH*NPs) return;
    int b = gid / NPs, p = gid % NPs;
    int y = p / Ws, x = p % Ws;

    const float* Eb = g_x + ((size_t)b*6 + 5)*NPs;
    float e = Eb[p];
    float gxv = (x > 0) ? e - Eb[p-1]  : 0.f;
    float gyv = (y > 0) ? e - Eb[p-Ws] : 0.f;
    float g = fminf(0.5f*(fabsf(gxv)+fabsf(gyv)), 1.f);
    float w = 0.7f * fminf(fmaxf(1.f - g*10.f, 0.f), 1.f);

    float cy = (y + 0.5f)*0.5f - 0.5f;
    float cx = (x + 0.5f)*0.5f - 0.5f;
    int y0 = (int)floorf(cy), x0 = (int)floorf(cx);
    float fy = cy - (float)y0, fx = cx - (float)x0;
    float wyv[2] = {1.f - fy, fy};
    float wxv[2] = {1.f - fx, fx};
    const float* Dpb = g_Dp + (size_t)b*Hp*Wp;
    float wsy = 0.f, wsx = 0.f;
#pragma unroll
    for (int a = 0; a < 2; a++) if (y0+a >= 0 && y0+a < Hp) wsy += wyv[a];
#pragma unroll
    for (int a = 0; a < 2; a++) if (x0+a >= 0 && x0+a < Wp) wsx += wxv[a];
    float acc = 0.f;
#pragma unroll
    for (int a = 0; a < 2; a++) {
        int yy = y0 + a;
        if (yy < 0 || yy >= Hp) continue;
#pragma unroll
        for (int c2 = 0; c2 < 2; c2++) {
            int xx = x0 + c2;
            if (xx < 0 || xx >= Wp) continue;
            acc += wyv[a]*wxv[c2]*Dpb[(size_t)yy*Wp + xx];
        }
    }
    float up = acc / (wsy * wsx);
    float P = fminf(e*10.f, 10.f);
    float D = w*up + (1.f - w)*P;
    g_D[(size_t)b*NPs + p] = D;
    g_f0[((size_t)b*65 + 64)*NPs + p] = D * 0.1f;
}

// ---------------- packed-f32x2 direct 3x3 conv, SAME padding, NCHW ----------------
#define CTW 32
#define CTH 8
#define CI_CHUNK 8

// MODE 0: relu + store COUT planes to out.
// MODE 1: fused head epilogue (COUT must be 32): normalize A, center, softmax gate, kappa.
template<int COUT, int MODE>
__global__ void __launch_bounds__(256, 2) conv3x3_f2_kernel(
    const float* __restrict__ in, const float* __restrict__ wT,
    const float* __restrict__ bias, float* __restrict__ out,
    int Cin, int inCtot, int outCtot, int Hs, int Ws) {
    __shared__ __align__(16) float s_in[CI_CHUNK][CTH+2][CTW+2];
    __shared__ __align__(16) float s_w[CI_CHUNK*9*COUT];

    int NPs = Hs*Ws;
    int b  = blockIdx.z;
    int x0 = blockIdx.x*CTW, y0 = blockIdx.y*CTH;
    int tx = threadIdx.x, ty = threadIdx.y;
    int tid = ty*CTW + tx;
    int x = x0 + tx, y = y0 + ty;

    unsigned long long acc2[COUT/2];
#pragma unroll
    for (int p = 0; p < COUT/2; p++) acc2[p] = pack2(bias[2*p], bias[2*p+1]);

    for (int ci0 = 0; ci0 < Cin; ci0 += CI_CHUNK) {
        int cc = min(CI_CHUNK, Cin - ci0);
        // stage weights (float4 vectorized; cc*9*COUT divisible by 4)
        {
            int nW4 = cc*9*COUT/4;
            const float4* wsrc = (const float4*)(wT + (size_t)ci0*9*COUT);
            float4* wdst = (float4*)s_w;
            for (int i = tid; i < nW4; i += CTW*CTH) wdst[i] = wsrc[i];
        }
        // stage input tile + halo
        {
            int nI = cc*(CTH+2)*(CTW+2);
            for (int i = tid; i < nI; i += CTW*CTH) {
                int c = i / ((CTH+2)*(CTW+2));
                int r = i % ((CTH+2)*(CTW+2));
                int iy = r / (CTW+2), ix = r % (CTW+2);
                int gy = y0 + iy - 1, gx = x0 + ix - 1;
                float v = 0.f;
                if (gy >= 0 && gy < Hs && gx >= 0 && gx < Ws)
                    v = in[((size_t)b*inCtot + ci0 + c)*NPs + (size_t)gy*Ws + gx];
                s_in[c][iy][ix] = v;
            }
        }
        __syncthreads();
        for (int ci = 0; ci < cc; ci++) {
            unsigned long long v2[9];
#pragma unroll
            for (int dy = 0; dy < 3; dy++)
#pragma unroll
                for (int dx = 0; dx < 3; dx++) {
                    float vv = s_in[ci][ty+dy][tx+dx];
                    v2[dy*3+dx] = pack2(vv, vv);
                }
            const unsigned long long* wp = (const unsigned long long*)(s_w + ci*9*COUT);
#pragma unroll
            for (int t = 0; t < 9; t++) {
                unsigned long long vv = v2[t];
#pragma unroll
                for (int p = 0; p < COUT/2; p++)
                    fma2(acc2[p], vv, wp[t*(COUT/2) + p]);
            }
        }
        __syncthreads();
    }

    if (x >= Ws || y >= Hs) return;
    size_t pp = (size_t)y*Ws + x;

    if (MODE == 0) {
        size_t o = (size_t)b*outCtot*NPs + pp;
#pragma unroll
        for (int p = 0; p < COUT/2; p++) {
            float lo, hi;
            unpack2(acc2[p], lo, hi);
            out[o + (size_t)(2*p  )*NPs] = fmaxf(lo, 0.f);
            out[o + (size_t)(2*p+1)*NPs] = fmaxf(hi, 0.f);
        }
    } else {
        // unpack 30 head values: 0-23 aff, 24-26 gate, 27-29 curv
        float a[32];
#pragma unroll
        for (int p = 0; p < COUT/2; p++) unpack2(acc2[p], a[2*p], a[2*p+1]);

        size_t Ab = (size_t)b*24*NPs + pp;
        size_t Cb = (size_t)b*9*NPs + pp;
#pragma unroll
        for (int k = 0; k < 3; k++) {
            float sab = 1e-6f;
#pragma unroll
            for (int j = 0; j < 8; j++) sab += fabsf(a[k*8+j]);
            float inv = 1.f / sab, sm = 0.f;
#pragma unroll
            for (int j = 0; j < 8; j++) {
                float an = a[k*8+j]*inv;
                g_A[Ab + (size_t)(k*8+j)*NPs] = an;
                sm += an;
            }
            g_csk[Cb + (size_t)k*NPs] = 1.f - sm;
        }
        float g0 = a[24], g1 = a[25], g2 = a[26];
        float m = fmaxf(g0, fmaxf(g1, g2));
        float e0 = expf(g0 - m), e1 = expf(g1 - m), e2 = expf(g2 - m);
        float inv = 1.f / (e0 + e1 + e2);
        g_csk[Cb + 3*(size_t)NPs] = e0*inv;
        g_csk[Cb + 4*(size_t)NPs] = e1*inv;
        g_csk[Cb + 5*(size_t)NPs] = e2*inv;
#pragma unroll
        for (int k = 0; k < 3; k++)
            g_csk[Cb + (size_t)(6+k)*NPs] = 0.1f + 0.9f / (1.f + expf(-a[27+k]));
    }
}

// ---------------- one propagation step ----------------
__global__ void prop_kernel(const float* __restrict__ Din, float* __restrict__ Dout,
                            int Hs, int Ws) {
    int NPs = Hs*Ws;
    int gid = blockIdx.x*blockDim.x + threadIdx.x;
    if (gid >= BATCH*NPs) return;
    int b = gid / NPs, p = gid % NPs;
    int y = p / Ws, x = p % Ws;
    const float* Db = Din + (size_t)b*NPs;
    float d = Db[p];
    size_t Ab = (size_t)b*24*NPs + p;
    size_t Cb = (size_t)b*9*NPs + p;
    const int offy[8] = {-1,-1,-1, 0, 0, 1, 1, 1};
    const int offx[8] = {-1, 0, 1,-1, 1,-1, 0, 1};
    const int dil[3]  = {1, 2, 4};
    float mix = 0.f;
#pragma unroll
    for (int k = 0; k < 3; k++) {
        float agg = g_csk[Cb + (size_t)k*NPs] * d;
        int dd = dil[k];
#pragma unroll
        for (int j = 0; j < 8; j++) {
            int ny = y + offy[j]*dd, nx = x + offx[j]*dd;
            float nb = (ny >= 0 && ny < Hs && nx >= 0 && nx < Ws) ? Db[(size_t)ny*Ws + nx] : 0.f;
            agg += g_A[Ab + (size_t)(k*8+j)*NPs] * nb;
        }
        float sig = g_csk[Cb + (size_t)(3+k)*NPs];
        float kap = g_csk[Cb + (size_t)(6+k)*NPs];
        mix += sig * (d + kap*(agg - d));
    }
    size_t xb = (size_t)b*6*NPs + p;
    float dls = g_x[xb + 3*(size_t)NPs];
    float mls = g_x[xb + 4*(size_t)NPs];
    Dout[(size_t)b*NPs + p] = mls*(0.9f*dls + 0.1f*mix) + (1.f - mls)*mix;
}

// ---------------- host orchestration ----------------
extern "C" void kernel_launch(void* const* d_in, const int* in_sizes, int n_in,
                              void* d_out, int out_size) {
    (void)in_sizes; (void)n_in; (void)out_size;
    const float* I  = (const float*)d_in[0];
    const float* DL = (const float*)d_in[1];
    const float* ML = (const float*)d_in[2];
    const float* E  = (const float*)d_in[3];
    const float* w0 = (const float*)d_in[4];
    const float* b0 = (const float*)d_in[5];
    const float* w1 = (const float*)d_in[6];
    const float* b1 = (const float*)d_in[7];
    const float* w2 = (const float*)d_in[8];
    const float* b2 = (const float*)d_in[9];
    const float* wa = (const float*)d_in[10];
    const float* ba = (const float*)d_in[11];
    const float* wg = (const float*)d_in[12];
    const float* bg = (const float*)d_in[13];
    const float* wc = (const float*)d_in[14];
    const float* bc = (const float*)d_in[15];
    float* out = (float*)d_out;

    float *px, *pf0, *pf1, *pD, *pD2, *pDp;
    float *pwT0, *pwT1, *pwT2, *pwTagc, *pbagc;
    cudaGetSymbolAddress((void**)&px,    g_x);
    cudaGetSymbolAddress((void**)&pf0,   g_f0);
    cudaGetSymbolAddress((void**)&pf1,   g_f1);
    cudaGetSymbolAddress((void**)&pD,    g_D);
    cudaGetSymbolAddress((void**)&pD2,   g_D2);
    cudaGetSymbolAddress((void**)&pDp,   g_Dp);
    cudaGetSymbolAddress((void**)&pwT0,  g_wT0);
    cudaGetSymbolAddress((void**)&pwT1,  g_wT1);
    cudaGetSymbolAddress((void**)&pwT2,  g_wT2);
    cudaGetSymbolAddress((void**)&pwTagc, g_wTagc);
    cudaGetSymbolAddress((void**)&pbagc, g_bagc);

    // weight prep (tiny)
    {
        int n;
        n = 64*6*9;  transpose_w_kernel<<<(n+255)/256, 256>>>(w0, pwT0, 64, 6);
        n = 64*64*9; transpose_w_kernel<<<(n+255)/256, 256>>>(w1, pwT1, 64, 64);
        n = 64*64*9; transpose_w_kernel<<<(n+255)/256, 256>>>(w2, pwT2, 64, 64);
        n = 65*9*32; build_agc_kernel<<<(n+255)/256, 256>>>(wa, ba, wg, bg, wc, bc);
    }

    const int SC[3] = {4, 2, 1};
    int Hp = 0, Wp = 0;
    for (int si = 0; si < 3; si++) {
        int S = SC[si];
        int Hs = H0 / S, Ws = W0 / S;
        int NPs = Hs * Ws;
        int tot = BATCH * NPs;
        int thr = 256, blk = (tot + thr - 1) / thr;

        if (si == 0) {
            prep_kernel<4, true><<<blk, thr>>>(I, DL, ML, E, Hs, Ws);
        } else if (si == 1) {
            prep_kernel<2, false><<<blk, thr>>>(I, DL, ML, E, Hs, Ws);
            init_d_kernel<<<blk, thr>>>(Hp, Wp, Hs, Ws);
        } else {
            prep_kernel<1, false><<<blk, thr>>>(I, DL, ML, E, Hs, Ws);
            init_d_kernel<<<blk, thr>>>(Hp, Wp, Hs, Ws);
        }

        dim3 cb(CTW, CTH);
        dim3 cg((Ws + CTW - 1)/CTW, (Hs + CTH - 1)/CTH, BATCH);
        // enc0: g_x(6) -> g_f0 ; enc1: g_f0 -> g_f1 ; enc2: g_f1 -> g_f0 (feat)
        conv3x3_f2_kernel<64, 0><<<cg, cb>>>(px,  pwT0, b0, pf0, 6,  6,  65, Hs, Ws);
        conv3x3_f2_kernel<64, 0><<<cg, cb>>>(pf0, pwT1, b1, pf1, 64, 65, 64, Hs, Ws);
        conv3x3_f2_kernel<64, 0><<<cg, cb>>>(pf1, pwT2, b2, pf0, 64, 64, 65, Hs, Ws);
        // fused aff+gate+curv conv + head epilogue (writes g_A, g_csk)
        conv3x3_f2_kernel<32, 1><<<cg, cb>>>(pf0, pwTagc, pbagc, nullptr, 65, 65, 0, Hs, Ws);

        float* Dc = pD;
        float* Dn = pD2;
        for (int st = 0; st < 6; st++) {
            prop_kernel<<<blk, thr>>>(Dc, Dn, Hs, Ws);
            float* t = Dc; Dc = Dn; Dn = t;
        }
        if (si < 2) {
            cudaMemcpyAsync(pDp, Dc, sizeof(float)*(size_t)BATCH*NPs, cudaMemcpyDeviceToDevice);
        } else {
            cudaMemcpyAsync(out, Dc, sizeof(float)*(size_t)BATCH*NPs, cudaMemcpyDeviceToDevice);
        }
        Hp = Hs; Wp = Ws;
    }
}

// round 4
// speedup vs baseline: 1.3263x; 1.1704x over previous
#include <cuda_runtime.h>
#include <math.h>

#define BATCH 2
#define H0 480
#define W0 640
#define NP0 (H0*W0)

// per-scale plane offsets: s=4 at 0 (19200), s=2 at 19200 (76800), s=1 at 96000 (307200)
#define PLANE 403200
#define OFF_S4 0
#define OFF_S2 19200
#define OFF_S1 96000

// ---------------- scratch (device globals) ----------------
__device__ float g_x   [BATCH*6 *PLANE];  // I(3), DLs, MLs, Es  (per-scale regions)
__device__ float g_A   [BATCH*24*PLANE];  // normalized affinities (per-scale)
__device__ float g_csk [BATCH*9 *PLANE];  // center(3), sigma(3), kappa(3) (per-scale)
__device__ float g_curv[BATCH*3 *PLANE];  // curv partial (feat part only) (per-scale)
__device__ float g_f0  [BATCH*64*NP0];    // feat ping
__device__ float g_f1  [BATCH*64*NP0];    // feat pong
__device__ float g_D   [BATCH*NP0];
__device__ float g_D2  [BATCH*NP0];
__device__ float g_Dp  [BATCH*NP0];

__device__ float g_wT0 [6 *9*64];
__device__ float g_wT1 [64*9*64];
__device__ float g_wT2 [64*9*64];
__device__ float g_wTagc[64*9*32];        // aff(24)+gate(3)+curv-feat(3)+pad(2)
__device__ float g_bagc[32];

// ---------------- f32x2 helpers ----------------
__device__ __forceinline__ void fma2(unsigned long long& d, unsigned long long a,
                                     unsigned long long b) {
    asm("fma.rn.f32x2 %0, %1, %2, %0;" : "+l"(d) : "l"(a), "l"(b));
}
__device__ __forceinline__ unsigned long long pack2(float lo, float hi) {
    unsigned long long r;
    asm("mov.b64 %0, {%1, %2};" : "=l"(r) : "f"(lo), "f"(hi));
    return r;
}
__device__ __forceinline__ void unpack2(unsigned long long v, float& lo, float& hi) {
    asm("mov.b64 {%0, %1}, %2;" : "=f"(lo), "=f"(hi) : "l"(v));
}

// ---------------- single weight-prep kernel (transposes + fused agc build) ----------------
__global__ void prep_weights(const float* __restrict__ w0, const float* __restrict__ w1,
                             const float* __restrict__ w2,
                             const float* __restrict__ wa, const float* __restrict__ ba,
                             const float* __restrict__ wg, const float* __restrict__ bg,
                             const float* __restrict__ wc, const float* __restrict__ bc) {
    int i = blockIdx.x*blockDim.x + threadIdx.x;
    if (i < 32) {
        float bv = 0.f;
        if (i < 24) bv = ba[i];
        else if (i < 27) bv = bg[i-24];
        else if (i < 30) bv = bc[i-27];
        g_bagc[i] = bv;
    }
    if (i < 3456) {                       // w0: (64,6,3,3)
        int co = i / 54, r = i % 54, ci = r / 9, t = r % 9;
        g_wT0[(ci*9 + t)*64 + co] = w0[i];
    } else if (i < 3456 + 36864) {        // w1
        int j = i - 3456;
        int co = j / 576, r = j % 576, ci = r / 9, t = r % 9;
        g_wT1[(ci*9 + t)*64 + co] = w1[j];
    } else if (i < 3456 + 73728) {        // w2
        int j = i - 40320;
        int co = j / 576, r = j % 576, ci = r / 9, t = r % 9;
        g_wT2[(ci*9 + t)*64 + co] = w2[j];
    } else if (i < 3456 + 73728 + 18432) { // agc: [ci(64)][t][co(32)]
        int j = i - 77184;
        int co = j % 32, t = (j / 32) % 9, ci = j / 288;
        float v = 0.f;
        if (co < 24)      v = wa[((size_t)co*64 + ci)*9 + t];
        else if (co < 27) v = wg[((size_t)(co-24)*64 + ci)*9 + t];
        else if (co < 30) v = wc[((size_t)(co-27)*65 + ci)*9 + t];
        g_wTagc[(ci*9 + t)*32 + co] = v;
    }
}

// ---------------- antialiased triangle-kernel downsample weights ----------------
template<int F>
__device__ __forceinline__ void down_weights(int i, int n, int& j0, float* w, float& ws) {
    float c = (float)(F*i) + 0.5f*(float)F - 0.5f;
    j0 = (int)ceilf(c - (float)F);
    ws = 0.f;
#pragma unroll
    for (int t = 0; t < 2*F; t++) {
        int j = j0 + t;
        float wv = (j >= 0 && j < n) ? (1.f - fabsf((float)j - c) * (1.f/(float)F)) : 0.f;
        w[t] = wv; ws += wv;
    }
}

// ---------------- per-scale prep ----------------
template<int S, bool FIRST>
__global__ void prep_kernel(const float* __restrict__ I, const float* __restrict__ DL,
                            const float* __restrict__ ML, const float* __restrict__ E,
                            int off, int Hs, int Ws) {
    int NPs = Hs*Ws;
    int gid = blockIdx.x*blockDim.x + threadIdx.x;
    if (gid >= BATCH*NPs) return;
    int b = gid / NPs, p = gid % NPs;
    int y = p / Ws, x = p % Ws;

    float iv0, iv1, iv2, ev;
    if (S == 1) {
        const float* Ib = I + (size_t)b*3*NP0;
        iv0 = Ib[p]; iv1 = Ib[NP0 + p]; iv2 = Ib[2*NP0 + p];
        ev  = E[(size_t)b*NP0 + p];
    } else {
        float wy[2*S], wx[2*S], wys, wxs;
        int jy0, jx0;
        down_weights<S>(y, H0, jy0, wy, wys);
        down_weights<S>(x, W0, jx0, wx, wxs);
        float a0=0.f, a1=0.f, a2=0.f, ae=0.f;
        const float* Ib = I + (size_t)b*3*NP0;
        const float* Eb = E + (size_t)b*NP0;
#pragma unroll
        for (int ty = 0; ty < 2*S; ty++) {
            int yy = jy0 + ty;
            if (yy < 0 || yy >= H0) continue;
            float wyv = wy[ty];
#pragma unroll
            for (int tx = 0; tx < 2*S; tx++) {
                int xx = jx0 + tx;
                if (xx < 0 || xx >= W0) continue;
                float wv = wyv * wx[tx];
                int q = yy*W0 + xx;
                a0 += wv*Ib[q];
                a1 += wv*Ib[NP0 + q];
                a2 += wv*Ib[2*NP0 + q];
                ae += wv*Eb[q];
            }
        }
        float inv = 1.f / (wys * wxs);
        iv0 = a0*inv; iv1 = a1*inv; iv2 = a2*inv; ev = ae*inv;
    }
    ev = fminf(fmaxf(ev, 0.f), 1.f);

    float dls, mls;
    if (S == 1) {
        mls = ML[(size_t)b*NP0 + p] > 0.f ? 1.f : 0.f;
        dls = DL[(size_t)b*NP0 + p];
    } else {
        float s = 0.f, c = 0.f;
        for (int dy = 0; dy < S; dy++)
            for (int dx = 0; dx < S; dx++) {
                int q = (y*S + dy)*W0 + (x*S + dx);
                float m = ML[(size_t)b*NP0 + q] > 0.f ? 1.f : 0.f;
                c += m;
                s += DL[(size_t)b*NP0 + q] * m;
            }
        mls = c > 0.f ? 1.f : 0.f;
        dls = c > 0.f ? s / (c + 1e-6f) : 0.f;
    }

    size_t xb = (size_t)b*6*PLANE + off;
    g_x[xb + 0*(size_t)PLANE + p] = iv0;
    g_x[xb + 1*(size_t)PLANE + p] = iv1;
    g_x[xb + 2*(size_t)PLANE + p] = iv2;
    g_x[xb + 3*(size_t)PLANE + p] = dls;
    g_x[xb + 4*(size_t)PLANE + p] = mls;
    g_x[xb + 5*(size_t)PLANE + p] = ev;
    if (FIRST) g_D[(size_t)b*NPs + p] = fminf(ev*10.f, 10.f);
}

// ---------------- init D from previous scale ----------------
__global__ void init_d_kernel(int off, int Hp, int Wp, int Hs, int Ws) {
    int NPs = Hs*Ws;
    int gid = blockIdx.x*blockDim.x + threadIdx.x;
    if (gid >= BATCH*NPs) return;
    int b = gid / NPs, p = gid % NPs;
    int y = p / Ws, x = p % Ws;

    const float* Eb = g_x + ((size_t)b*6 + 5)*PLANE + off;
    float e = Eb[p];
    float gxv = (x > 0) ? e - Eb[p-1]  : 0.f;
    float gyv = (y > 0) ? e - Eb[p-Ws] : 0.f;
    float g = fminf(0.5f*(fabsf(gxv)+fabsf(gyv)), 1.f);
    float w = 0.7f * fminf(fmaxf(1.f - g*10.f, 0.f), 1.f);

    float cy = (y + 0.5f)*0.5f - 0.5f;
    float cx = (x + 0.5f)*0.5f - 0.5f;
    int y0 = (int)floorf(cy), x0 = (int)floorf(cx);
    float fy = cy - (float)y0, fx = cx - (float)x0;
    float wyv[2] = {1.f - fy, fy};
    float wxv[2] = {1.f - fx, fx};
    const float* Dpb = g_Dp + (size_t)b*Hp*Wp;
    float wsy = 0.f, wsx = 0.f;
#pragma unroll
    for (int a = 0; a < 2; a++) if (y0+a >= 0 && y0+a < Hp) wsy += wyv[a];
#pragma unroll
    for (int a = 0; a < 2; a++) if (x0+a >= 0 && x0+a < Wp) wsx += wxv[a];
    float acc = 0.f;
#pragma unroll
    for (int a = 0; a < 2; a++) {
        int yy = y0 + a;
        if (yy < 0 || yy >= Hp) continue;
#pragma unroll
        for (int c2 = 0; c2 < 2; c2++) {
            int xx = x0 + c2;
            if (xx < 0 || xx >= Wp) continue;
            acc += wyv[a]*wxv[c2]*Dpb[(size_t)yy*Wp + xx];
        }
    }
    float up = acc / (wsy * wsx);
    float P = fminf(e*10.f, 10.f);
    g_D[(size_t)b*NPs + p] = w*up + (1.f - w)*P;
}

// ---------------- conv 3x3: 2 pixels/thread, LDS.128 weights, f32x2 FMA ----------------
#define CTW 32
#define CTH2 16
#define CI_CHUNK 8

// MODE 0: relu + store COUT planes. MODE 1: fused head epilogue (COUT=32).
template<int COUT, int MODE>
__global__ void __launch_bounds__(256, 1) conv3x3_kernel(
    const float* __restrict__ in, int inPS, int inOff, int inCtot, int Cin,
    const float* __restrict__ wT, const float* __restrict__ bias,
    float* __restrict__ out, int outPS, int outOff,
    int Hs, int Ws) {
    __shared__ __align__(16) float s_in[CI_CHUNK][CTH2+2][CTW+2];
    __shared__ __align__(16) float s_w[CI_CHUNK*9*COUT];

    int b  = blockIdx.z;
    int x0 = blockIdx.x*CTW, y0 = blockIdx.y*CTH2;
    int tx = threadIdx.x, ty = threadIdx.y;
    int tid = ty*CTW + tx;
    int x = x0 + tx;
    int yA = y0 + ty, yB = yA + 8;

    unsigned long long accA[COUT/2], accB[COUT/2];
#pragma unroll
    for (int p = 0; p < COUT/2; p++) {
        unsigned long long bv = pack2(bias[2*p], bias[2*p+1]);
        accA[p] = bv; accB[p] = bv;
    }

    for (int ci0 = 0; ci0 < Cin; ci0 += CI_CHUNK) {
        int cc = min(CI_CHUNK, Cin - ci0);
        {
            int nW4 = cc*9*COUT/4;
            const float4* wsrc = (const float4*)(wT + (size_t)ci0*9*COUT);
            float4* wdst = (float4*)s_w;
            for (int i = tid; i < nW4; i += 256) wdst[i] = wsrc[i];
        }
        {
            int nI = cc*(CTH2+2)*(CTW+2);
            for (int i = tid; i < nI; i += 256) {
                int c = i / ((CTH2+2)*(CTW+2));
                int r = i % ((CTH2+2)*(CTW+2));
                int iy = r / (CTW+2), ix = r % (CTW+2);
                int gy = y0 + iy - 1, gx = x0 + ix - 1;
                float v = 0.f;
                if (gy >= 0 && gy < Hs && gx >= 0 && gx < Ws)
                    v = in[((size_t)b*inCtot + ci0 + c)*inPS + inOff + (size_t)gy*Ws + gx];
                s_in[c][iy][ix] = v;
            }
        }
        __syncthreads();
        for (int ci = 0; ci < cc; ci++) {
#pragma unroll
            for (int t = 0; t < 9; t++) {
                int dy = t/3, dx = t%3;
                float a0 = s_in[ci][ty+dy][tx+dx];
                float a1 = s_in[ci][ty+8+dy][tx+dx];
                unsigned long long v0 = pack2(a0, a0);
                unsigned long long v1 = pack2(a1, a1);
                const ulonglong2* wp = (const ulonglong2*)(s_w + (ci*9 + t)*COUT);
#pragma unroll
                for (int q = 0; q < COUT/4; q++) {
                    ulonglong2 wv = wp[q];
                    fma2(accA[2*q],   v0, wv.x);
                    fma2(accA[2*q+1], v0, wv.y);
                    fma2(accB[2*q],   v1, wv.x);
                    fma2(accB[2*q+1], v1, wv.y);
                }
            }
        }
        __syncthreads();
    }

    if (x >= Ws) return;

#pragma unroll
    for (int px = 0; px < 2; px++) {
        int y = px ? yB : yA;
        if (y >= Hs) continue;
        unsigned long long* acc = px ? accB : accA;
        size_t pp = (size_t)y*Ws + x;
        if (MODE == 0) {
            size_t o = (size_t)b*64*outPS + outOff + pp;   // outCtot == 64 for MODE 0
#pragma unroll
            for (int p = 0; p < COUT/2; p++) {
                float lo, hi;
                unpack2(acc[p], lo, hi);
                out[o + (size_t)(2*p  )*outPS] = fmaxf(lo, 0.f);
                out[o + (size_t)(2*p+1)*outPS] = fmaxf(hi, 0.f);
            }
        } else {
            float a[32];
#pragma unroll
            for (int p = 0; p < COUT/2; p++) unpack2(acc[p], a[2*p], a[2*p+1]);
            int off = outOff;
            size_t Ab = (size_t)b*24*PLANE + off + pp;
            size_t Cb = (size_t)b*9*PLANE + off + pp;
#pragma unroll
            for (int k = 0; k < 3; k++) {
                float sab = 1e-6f;
#pragma unroll
                for (int j = 0; j < 8; j++) sab += fabsf(a[k*8+j]);
                float inv = 1.f / sab, sm = 0.f;
#pragma unroll
                for (int j = 0; j < 8; j++) {
                    float an = a[k*8+j]*inv;
                    g_A[Ab + (size_t)(k*8+j)*PLANE] = an;
                    sm += an;
                }
                g_csk[Cb + (size_t)k*PLANE] = 1.f - sm;
            }
            float g0 = a[24], g1 = a[25], g2 = a[26];
            float m = fmaxf(g0, fmaxf(g1, g2));
            float e0 = expf(g0 - m), e1 = expf(g1 - m), e2 = expf(g2 - m);
            float inv = 1.f / (e0 + e1 + e2);
            g_csk[Cb + 3*(size_t)PLANE] = e0*inv;
            g_csk[Cb + 4*(size_t)PLANE] = e1*inv;
            g_csk[Cb + 5*(size_t)PLANE] = e2*inv;
            size_t Vb = (size_t)b*3*PLANE + off + pp;
#pragma unroll
            for (int k = 0; k < 3; k++)
                g_curv[Vb + (size_t)k*PLANE] = a[27+k];
        }
    }
}

// ---------------- curv D-part: kappa = 0.1+0.9*sigmoid(curv_partial + conv(D*0.1, wc[:,64])) ----------------
__global__ void curvd_kernel(const float* __restrict__ wc, int off, int Hs, int Ws) {
    int NPs = Hs*Ws;
    int gid = blockIdx.x*blockDim.x + threadIdx.x;
    if (gid >= BATCH*NPs) return;
    int b = gid / NPs, p = gid % NPs;
    int y = p / Ws, x = p % Ws;
    const float* Db = g_D + (size_t)b*NPs;
    float dnb[9];
#pragma unroll
    for (int t = 0; t < 9; t++) {
        int dy = t/3 - 1, dx = t%3 - 1;
        int ny = y + dy, nx = x + dx;
        dnb[t] = (ny >= 0 && ny < Hs && nx >= 0 && nx < Ws) ? Db[(size_t)ny*Ws + nx]*0.1f : 0.f;
    }
    size_t Vb = (size_t)b*3*PLANE + off + p;
    size_t Cb = (size_t)b*9*PLANE + off + p;
#pragma unroll
    for (int co = 0; co < 3; co++) {
        float v = g_curv[Vb + (size_t)co*PLANE];
#pragma unroll
        for (int t = 0; t < 9; t++)
            v += wc[((size_t)co*65 + 64)*9 + t] * dnb[t];
        g_csk[Cb + (size_t)(6+co)*PLANE] = 0.1f + 0.9f/(1.f + expf(-v));
    }
}

// ---------------- one propagation step ----------------
__global__ void prop_kernel(const float* __restrict__ Din, float* __restrict__ Dout,
                            int off, int Hs, int Ws) {
    int NPs = Hs*Ws;
    int gid = blockIdx.x*blockDim.x + threadIdx.x;
    if (gid >= BATCH*NPs) return;
    int b = gid / NPs, p = gid % NPs;
    int y = p / Ws, x = p % Ws;
    const float* Db = Din + (size_t)b*NPs;
    float d = Db[p];
    size_t Ab = (size_t)b*24*PLANE + off + p;
    size_t Cb = (size_t)b*9*PLANE + off + p;
    const int offy[8] = {-1,-1,-1, 0, 0, 1, 1, 1};
    const int offx[8] = {-1, 0, 1,-1, 1,-1, 0, 1};
    const int dil[3]  = {1, 2, 4};
    float mix = 0.f;
#pragma unroll
    for (int k = 0; k < 3; k++) {
        float agg = g_csk[Cb + (size_t)k*PLANE] * d;
        int dd = dil[k];
#pragma unroll
        for (int j = 0; j < 8; j++) {
            int ny = y + offy[j]*dd, nx = x + offx[j]*dd;
            float nb = (ny >= 0 && ny < Hs && nx >= 0 && nx < Ws) ? Db[(size_t)ny*Ws + nx] : 0.f;
            agg += g_A[Ab + (size_t)(k*8+j)*PLANE] * nb;
        }
        float sig = g_csk[Cb + (size_t)(3+k)*PLANE];
        float kap = g_csk[Cb + (size_t)(6+k)*PLANE];
        mix += sig * (d + kap*(agg - d));
    }
    size_t xb = (size_t)b*6*PLANE + off + p;
    float dls = g_x[xb + 3*(size_t)PLANE];
    float mls = g_x[xb + 4*(size_t)PLANE];
    Dout[(size_t)b*NPs + p] = mls*(0.9f*dls + 0.1f*mix) + (1.f - mls)*mix;
}

// ---------------- host orchestration ----------------
extern "C" void kernel_launch(void* const* d_in, const int* in_sizes, int n_in,
                              void* d_out, int out_size) {
    (void)in_sizes; (void)n_in; (void)out_size;
    const float* I  = (const float*)d_in[0];
    const float* DL = (const float*)d_in[1];
    const float* ML = (const float*)d_in[2];
    const float* E  = (const float*)d_in[3];
    const float* w0 = (const float*)d_in[4];
    const float* b0 = (const float*)d_in[5];
    const float* w1 = (const float*)d_in[6];
    const float* b1 = (const float*)d_in[7];
    const float* w2 = (const float*)d_in[8];
    const float* b2 = (const float*)d_in[9];
    const float* wa = (const float*)d_in[10];
    const float* ba = (const float*)d_in[11];
    const float* wg = (const float*)d_in[12];
    const float* bg = (const float*)d_in[13];
    const float* wc = (const float*)d_in[14];
    const float* bc = (const float*)d_in[15];
    float* out = (float*)d_out;

    float *px, *pf0, *pf1, *pD, *pD2, *pDp;
    float *pwT0, *pwT1, *pwT2, *pwTagc, *pbagc;
    cudaGetSymbolAddress((void**)&px,    g_x);
    cudaGetSymbolAddress((void**)&pf0,   g_f0);
    cudaGetSymbolAddress((void**)&pf1,   g_f1);
    cudaGetSymbolAddress((void**)&pD,    g_D);
    cudaGetSymbolAddress((void**)&pD2,   g_D2);
    cudaGetSymbolAddress((void**)&pDp,   g_Dp);
    cudaGetSymbolAddress((void**)&pwT0,  g_wT0);
    cudaGetSymbolAddress((void**)&pwT1,  g_wT1);
    cudaGetSymbolAddress((void**)&pwT2,  g_wT2);
    cudaGetSymbolAddress((void**)&pwTagc, g_wTagc);
    cudaGetSymbolAddress((void**)&pbagc, g_bagc);

    const int SC[3]   = {4, 2, 1};
    const int OFFS[3] = {OFF_S4, OFF_S2, OFF_S1};

    // 1) all weight prep in ONE kernel
    prep_weights<<<(95616 + 255)/256, 256>>>(w0, w1, w2, wa, ba, wg, bg, wc, bc);

    // 2-4) per-scale input prep (s=1 first so convs land early for ncu)
    {
        int Hs, Ws, tot;
        Hs = H0; Ws = W0; tot = BATCH*Hs*Ws;
        prep_kernel<1, false><<<(tot+255)/256, 256>>>(I, DL, ML, E, OFF_S1, Hs, Ws);
        Hs = H0/2; Ws = W0/2; tot = BATCH*Hs*Ws;
        prep_kernel<2, false><<<(tot+255)/256, 256>>>(I, DL, ML, E, OFF_S2, Hs, Ws);
        Hs = H0/4; Ws = W0/4; tot = BATCH*Hs*Ws;
        prep_kernel<4, true><<<(tot+255)/256, 256>>>(I, DL, ML, E, OFF_S4, Hs, Ws);
    }

    // 5..16) all heavy convs, s=1 first (launches 5-8 are the big ones)
    for (int si = 2; si >= 0; si--) {   // si index into SC: process s=1, s=2, s=4
        int S = SC[si];
        int off = OFFS[si];
        int Hs = H0/S, Ws = W0/S, NPs = Hs*Ws;
        dim3 cb(CTW, 8);
        dim3 cg(Ws/CTW, (Hs + CTH2 - 1)/CTH2, BATCH);
        // enc0: g_x(6ch, PLANE-stride) -> f0 ; enc1: f0 -> f1 ; enc2: f1 -> f0
        conv3x3_kernel<64, 0><<<cg, cb>>>(px,  PLANE, off, 6,  6,  pwT0, b0, pf0, NPs, 0, Hs, Ws);
        conv3x3_kernel<64, 0><<<cg, cb>>>(pf0, NPs,   0,  64, 64, pwT1, b1, pf1, NPs, 0, Hs, Ws);
        conv3x3_kernel<64, 0><<<cg, cb>>>(pf1, NPs,   0,  64, 64, pwT2, b2, pf0, NPs, 0, Hs, Ws);
        // fused aff+gate+curv(feat part) + head epilogue
        conv3x3_kernel<32, 1><<<cg, cb>>>(pf0, NPs,   0,  64, 64, pwTagc, pbagc, nullptr, 0, off, Hs, Ws);
    }

    // propagation chain: coarse-to-fine
    int Hp = 0, Wp = 0;
    for (int si = 0; si < 3; si++) {
        int S = SC[si];
        int off = OFFS[si];
        int Hs = H0/S, Ws = W0/S, NPs = Hs*Ws;
        int tot = BATCH*NPs, blk = (tot + 255)/256;

        if (si > 0) init_d_kernel<<<blk, 256>>>(off, Hp, Wp, Hs, Ws);
        curvd_kernel<<<blk, 256>>>(wc, off, Hs, Ws);

        float* Dc = pD;
        float* Dn = pD2;
        for (int st = 0; st < 6; st++) {
            prop_kernel<<<blk, 256>>>(Dc, Dn, off, Hs, Ws);
            float* t = Dc; Dc = Dn; Dn = t;
        }
        if (si < 2) {
            cudaMemcpyAsync(pDp, Dc, sizeof(float)*(size_t)BATCH*NPs, cudaMemcpyDeviceToDevice);
        } else {
            cudaMemcpyAsync(out, Dc, sizeof(float)*(size_t)BATCH*NPs, cudaMemcpyDeviceToDevice);
        }
        Hp = Hs; Wp = Ws;
    }
}

// round 5
// speedup vs baseline: 1.4238x; 1.0735x over previous
#include <cuda_runtime.h>
#include <math.h>

#define BATCH 2
#define H0 480
#define W0 640
#define NP0 (H0*W0)

// per-scale plane offsets: s=4 at 0 (19200), s=2 at 19200 (76800), s=1 at 96000 (307200)
#define PLANE 403200
#define OFF_S4 0
#define OFF_S2 19200
#define OFF_S1 96000

// ---------------- scratch (device globals) ----------------
__device__ float g_x   [BATCH*6 *PLANE];
__device__ float g_A   [BATCH*24*PLANE];
__device__ float g_csk [BATCH*9 *PLANE];
__device__ float g_curv[BATCH*3 *PLANE];
__device__ float g_f0  [BATCH*64*NP0];
__device__ float g_f1  [BATCH*64*NP0];
__device__ float g_D   [BATCH*NP0];
__device__ float g_D2  [BATCH*NP0];
__device__ float g_Dp  [BATCH*NP0];

__device__ float g_wT0 [6 *9*64];
__device__ float g_wT1 [64*9*64];
__device__ float g_wT2 [64*9*64];
__device__ float g_wTagc[64*9*32];        // aff(24)+gate(3)+curv-feat(3)+pad(2)
__device__ float g_bagc[32];

// ---------------- f32x2 helpers ----------------
__device__ __forceinline__ void fma2(unsigned long long& d, unsigned long long a,
                                     unsigned long long b) {
    asm("fma.rn.f32x2 %0, %1, %2, %0;" : "+l"(d) : "l"(a), "l"(b));
}
__device__ __forceinline__ unsigned long long pack2(float lo, float hi) {
    unsigned long long r;
    asm("mov.b64 %0, {%1, %2};" : "=l"(r) : "f"(lo), "f"(hi));
    return r;
}
__device__ __forceinline__ void unpack2(unsigned long long v, float& lo, float& hi) {
    asm("mov.b64 {%0, %1}, %2;" : "=f"(lo), "=f"(hi) : "l"(v));
}

// ---------------- single weight-prep kernel ----------------
__global__ void prep_weights(const float* __restrict__ w0, const float* __restrict__ w1,
                             const float* __restrict__ w2,
                             const float* __restrict__ wa, const float* __restrict__ ba,
                             const float* __restrict__ wg, const float* __restrict__ bg,
                             const float* __restrict__ wc, const float* __restrict__ bc) {
    int i = blockIdx.x*blockDim.x + threadIdx.x;
    if (i < 32) {
        float bv = 0.f;
        if (i < 24) bv = ba[i];
        else if (i < 27) bv = bg[i-24];
        else if (i < 30) bv = bc[i-27];
        g_bagc[i] = bv;
    }
    if (i < 3456) {                       // w0: (64,6,3,3)
        int co = i / 54, r = i % 54, ci = r / 9, t = r % 9;
        g_wT0[(ci*9 + t)*64 + co] = w0[i];
    } else if (i < 3456 + 36864) {        // w1
        int j = i - 3456;
        int co = j / 576, r = j % 576, ci = r / 9, t = r % 9;
        g_wT1[(ci*9 + t)*64 + co] = w1[j];
    } else if (i < 3456 + 73728) {        // w2
        int j = i - 40320;
        int co = j / 576, r = j % 576, ci = r / 9, t = r % 9;
        g_wT2[(ci*9 + t)*64 + co] = w2[j];
    } else if (i < 3456 + 73728 + 18432) { // agc: [ci(64)][t][co(32)]
        int j = i - 77184;
        int co = j % 32, t = (j / 32) % 9, ci = j / 288;
        float v = 0.f;
        if (co < 24)      v = wa[((size_t)co*64 + ci)*9 + t];
        else if (co < 27) v = wg[((size_t)(co-24)*64 + ci)*9 + t];
        else if (co < 30) v = wc[((size_t)(co-27)*65 + ci)*9 + t];
        g_wTagc[(ci*9 + t)*32 + co] = v;
    }
}

// ---------------- antialiased triangle-kernel downsample weights ----------------
template<int F>
__device__ __forceinline__ void down_weights(int i, int n, int& j0, float* w, float& ws) {
    float c = (float)(F*i) + 0.5f*(float)F - 0.5f;
    j0 = (int)ceilf(c - (float)F);
    ws = 0.f;
#pragma unroll
    for (int t = 0; t < 2*F; t++) {
        int j = j0 + t;
        float wv = (j >= 0 && j < n) ? (1.f - fabsf((float)j - c) * (1.f/(float)F)) : 0.f;
        w[t] = wv; ws += wv;
    }
}

// ---------------- per-scale prep ----------------
template<int S, bool FIRST>
__global__ void prep_kernel(const float* __restrict__ I, const float* __restrict__ DL,
                            const float* __restrict__ ML, const float* __restrict__ E,
                            int off, int Hs, int Ws) {
    int NPs = Hs*Ws;
    int gid = blockIdx.x*blockDim.x + threadIdx.x;
    if (gid >= BATCH*NPs) return;
    int b = gid / NPs, p = gid % NPs;
    int y = p / Ws, x = p % Ws;

    float iv0, iv1, iv2, ev;
    if (S == 1) {
        const float* Ib = I + (size_t)b*3*NP0;
        iv0 = Ib[p]; iv1 = Ib[NP0 + p]; iv2 = Ib[2*NP0 + p];
        ev  = E[(size_t)b*NP0 + p];
    } else {
        float wy[2*S], wx[2*S], wys, wxs;
        int jy0, jx0;
        down_weights<S>(y, H0, jy0, wy, wys);
        down_weights<S>(x, W0, jx0, wx, wxs);
        float a0=0.f, a1=0.f, a2=0.f, ae=0.f;
        const float* Ib = I + (size_t)b*3*NP0;
        const float* Eb = E + (size_t)b*NP0;
#pragma unroll
        for (int ty = 0; ty < 2*S; ty++) {
            int yy = jy0 + ty;
            if (yy < 0 || yy >= H0) continue;
            float wyv = wy[ty];
#pragma unroll
            for (int tx = 0; tx < 2*S; tx++) {
                int xx = jx0 + tx;
                if (xx < 0 || xx >= W0) continue;
                float wv = wyv * wx[tx];
                int q = yy*W0 + xx;
                a0 += wv*Ib[q];
                a1 += wv*Ib[NP0 + q];
                a2 += wv*Ib[2*NP0 + q];
                ae += wv*Eb[q];
            }
        }
        float inv = 1.f / (wys * wxs);
        iv0 = a0*inv; iv1 = a1*inv; iv2 = a2*inv; ev = ae*inv;
    }
    ev = fminf(fmaxf(ev, 0.f), 1.f);

    float dls, mls;
    if (S == 1) {
        mls = ML[(size_t)b*NP0 + p] > 0.f ? 1.f : 0.f;
        dls = DL[(size_t)b*NP0 + p];
    } else {
        float s = 0.f, c = 0.f;
        for (int dy = 0; dy < S; dy++)
            for (int dx = 0; dx < S; dx++) {
                int q = (y*S + dy)*W0 + (x*S + dx);
                float m = ML[(size_t)b*NP0 + q] > 0.f ? 1.f : 0.f;
                c += m;
                s += DL[(size_t)b*NP0 + q] * m;
            }
        mls = c > 0.f ? 1.f : 0.f;
        dls = c > 0.f ? s / (c + 1e-6f) : 0.f;
    }

    size_t xb = (size_t)b*6*PLANE + off;
    g_x[xb + 0*(size_t)PLANE + p] = iv0;
    g_x[xb + 1*(size_t)PLANE + p] = iv1;
    g_x[xb + 2*(size_t)PLANE + p] = iv2;
    g_x[xb + 3*(size_t)PLANE + p] = dls;
    g_x[xb + 4*(size_t)PLANE + p] = mls;
    g_x[xb + 5*(size_t)PLANE + p] = ev;
    if (FIRST) g_D[(size_t)b*NPs + p] = fminf(ev*10.f, 10.f);
}

// ---------------- init D from previous scale ----------------
__global__ void init_d_kernel(int off, int Hp, int Wp, int Hs, int Ws) {
    int NPs = Hs*Ws;
    int gid = blockIdx.x*blockDim.x + threadIdx.x;
    if (gid >= BATCH*NPs) return;
    int b = gid / NPs, p = gid % NPs;
    int y = p / Ws, x = p % Ws;

    const float* Eb = g_x + ((size_t)b*6 + 5)*PLANE + off;
    float e = Eb[p];
    float gxv = (x > 0) ? e - Eb[p-1]  : 0.f;
    float gyv = (y > 0) ? e - Eb[p-Ws] : 0.f;
    float g = fminf(0.5f*(fabsf(gxv)+fabsf(gyv)), 1.f);
    float w = 0.7f * fminf(fmaxf(1.f - g*10.f, 0.f), 1.f);

    float cy = (y + 0.5f)*0.5f - 0.5f;
    float cx = (x + 0.5f)*0.5f - 0.5f;
    int y0 = (int)floorf(cy), x0 = (int)floorf(cx);
    float fy = cy - (float)y0, fx = cx - (float)x0;
    float wyv[2] = {1.f - fy, fy};
    float wxv[2] = {1.f - fx, fx};
    const float* Dpb = g_Dp + (size_t)b*Hp*Wp;
    float wsy = 0.f, wsx = 0.f;
#pragma unroll
    for (int a = 0; a < 2; a++) if (y0+a >= 0 && y0+a < Hp) wsy += wyv[a];
#pragma unroll
    for (int a = 0; a < 2; a++) if (x0+a >= 0 && x0+a < Wp) wsx += wxv[a];
    float acc = 0.f;
#pragma unroll
    for (int a = 0; a < 2; a++) {
        int yy = y0 + a;
        if (yy < 0 || yy >= Hp) continue;
#pragma unroll
        for (int c2 = 0; c2 < 2; c2++) {
            int xx = x0 + c2;
            if (xx < 0 || xx >= Wp) continue;
            acc += wyv[a]*wxv[c2]*Dpb[(size_t)yy*Wp + xx];
        }
    }
    float up = acc / (wsy * wsx);
    float P = fminf(e*10.f, 10.f);
    g_D[(size_t)b*NPs + p] = w*up + (1.f - w)*P;
}

// ---------------- conv 3x3: 4 pixels x COUT/2 outputs per thread ----------------
#define CTW 32
#define CTH2 16
#define CI_CHUNK 8

// block (32,8): r = ty&3 (pixel row), h = ty>>2 (co half).
// MODE 0: relu + store. MODE 1: fused head epilogue (COUT=32).
template<int COUT, int MODE>
__global__ void __launch_bounds__(256, 1) conv3x3_kernel(
    const float* __restrict__ in, int inPS, int inOff, int inCtot, int Cin,
    const float* __restrict__ wT, const float* __restrict__ bias,
    float* __restrict__ out, int outPS, int outOff,
    int Hs, int Ws) {
    const int NCO = COUT/2;
    __shared__ __align__(16) float s_in[CI_CHUNK][CTH2+2][CTW+2];
    __shared__ __align__(16) float s_w[CI_CHUNK*9*COUT];

    int b  = blockIdx.z;
    int x0 = blockIdx.x*CTW, y0 = blockIdx.y*CTH2;
    int tx = threadIdx.x, ty = threadIdx.y;
    int tid = ty*CTW + tx;
    int r = ty & 3, h = ty >> 2;
    int x = x0 + tx;

    unsigned long long acc[4][NCO/2];
#pragma unroll
    for (int p = 0; p < NCO/2; p++) {
        unsigned long long bv = pack2(bias[h*NCO + 2*p], bias[h*NCO + 2*p + 1]);
#pragma unroll
        for (int i = 0; i < 4; i++) acc[i][p] = bv;
    }

    for (int ci0 = 0; ci0 < Cin; ci0 += CI_CHUNK) {
        int cc = min(CI_CHUNK, Cin - ci0);
        {
            int nW4 = cc*9*COUT/4;
            const float4* wsrc = (const float4*)(wT + (size_t)ci0*9*COUT);
            float4* wdst = (float4*)s_w;
            for (int i = tid; i < nW4; i += 256) wdst[i] = wsrc[i];
        }
        {
            int nI = cc*(CTH2+2)*(CTW+2);
            for (int i = tid; i < nI; i += 256) {
                int c = i / ((CTH2+2)*(CTW+2));
                int rr = i % ((CTH2+2)*(CTW+2));
                int iy = rr / (CTW+2), ix = rr % (CTW+2);
                int gy = y0 + iy - 1, gx = x0 + ix - 1;
                float v = 0.f;
                if (gy >= 0 && gy < Hs && gx >= 0 && gx < Ws)
                    v = in[((size_t)b*inCtot + ci0 + c)*inPS + inOff + (size_t)gy*Ws + gx];
                s_in[c][iy][ix] = v;
            }
        }
        __syncthreads();
        for (int ci = 0; ci < cc; ci++) {
#pragma unroll
            for (int t = 0; t < 9; t++) {
                int dy = t/3, dx = t%3;
                unsigned long long v[4];
#pragma unroll
                for (int i = 0; i < 4; i++) {
                    float av = s_in[ci][r + 4*i + dy][tx + dx];
                    v[i] = pack2(av, av);
                }
                const ulonglong2* wp = (const ulonglong2*)(s_w + (ci*9 + t)*COUT + h*NCO);
#pragma unroll
                for (int q = 0; q < NCO/4; q++) {
                    ulonglong2 wv = wp[q];
#pragma unroll
                    for (int i = 0; i < 4; i++) {
                        fma2(acc[i][2*q],   v[i], wv.x);
                        fma2(acc[i][2*q+1], v[i], wv.y);
                    }
                }
            }
        }
        __syncthreads();
    }

    if (x >= Ws) return;

#pragma unroll
    for (int i = 0; i < 4; i++) {
        int y = y0 + r + 4*i;
        if (y >= Hs) continue;
        size_t pp = (size_t)y*Ws + x;
        if (MODE == 0) {
            size_t o = (size_t)b*64*outPS + outOff + pp;
#pragma unroll
            for (int p = 0; p < NCO/2; p++) {
                float lo, hi;
                unpack2(acc[i][p], lo, hi);
                out[o + (size_t)(h*NCO + 2*p    )*outPS] = fmaxf(lo, 0.f);
                out[o + (size_t)(h*NCO + 2*p + 1)*outPS] = fmaxf(hi, 0.f);
            }
        } else {
            // COUT=32, NCO=16. h=0: co0-15 = aff k0,k1. h=1: co16-31 = aff k2, gate, curv.
            float a[16];
#pragma unroll
            for (int p = 0; p < 8; p++) unpack2(acc[i][p], a[2*p], a[2*p+1]);
            int off = outOff;
            size_t Ab = (size_t)b*24*PLANE + off + pp;
            size_t Cb = (size_t)b*9*PLANE + off + pp;
            if (h == 0) {
#pragma unroll
                for (int k = 0; k < 2; k++) {
                    float sab = 1e-6f;
#pragma unroll
                    for (int j = 0; j < 8; j++) sab += fabsf(a[k*8+j]);
                    float inv = 1.f / sab, sm = 0.f;
#pragma unroll
                    for (int j = 0; j < 8; j++) {
                        float an = a[k*8+j]*inv;
                        g_A[Ab + (size_t)(k*8+j)*PLANE] = an;
                        sm += an;
                    }
                    g_csk[Cb + (size_t)k*PLANE] = 1.f - sm;
                }
            } else {
                {   // k=2 affinities (a[0..7])
                    float sab = 1e-6f;
#pragma unroll
                    for (int j = 0; j < 8; j++) sab += fabsf(a[j]);
                    float inv = 1.f / sab, sm = 0.f;
#pragma unroll
                    for (int j = 0; j < 8; j++) {
                        float an = a[j]*inv;
                        g_A[Ab + (size_t)(16+j)*PLANE] = an;
                        sm += an;
                    }
                    g_csk[Cb + 2*(size_t)PLANE] = 1.f - sm;
                }
                float g0 = a[8], g1 = a[9], g2 = a[10];
                float m = fmaxf(g0, fmaxf(g1, g2));
                float e0 = expf(g0 - m), e1 = expf(g1 - m), e2 = expf(g2 - m);
                float inv = 1.f / (e0 + e1 + e2);
                g_csk[Cb + 3*(size_t)PLANE] = e0*inv;
                g_csk[Cb + 4*(size_t)PLANE] = e1*inv;
                g_csk[Cb + 5*(size_t)PLANE] = e2*inv;
                size_t Vb = (size_t)b*3*PLANE + off + pp;
#pragma unroll
                for (int k = 0; k < 3; k++)
                    g_curv[Vb + (size_t)k*PLANE] = a[11+k];
            }
        }
    }
}

// ---------------- curv D-part ----------------
__global__ void curvd_kernel(const float* __restrict__ wc, int off, int Hs, int Ws) {
    int NPs = Hs*Ws;
    int gid = blockIdx.x*blockDim.x + threadIdx.x;
    if (gid >= BATCH*NPs) return;
    int b = gid / NPs, p = gid % NPs;
    int y = p / Ws, x = p % Ws;
    const float* Db = g_D + (size_t)b*NPs;
    float dnb[9];
#pragma unroll
    for (int t = 0; t < 9; t++) {
        int dy = t/3 - 1, dx = t%3 - 1;
        int ny = y + dy, nx = x + dx;
        dnb[t] = (ny >= 0 && ny < Hs && nx >= 0 && nx < Ws) ? Db[(size_t)ny*Ws + nx]*0.1f : 0.f;
    }
    size_t Vb = (size_t)b*3*PLANE + off + p;
    size_t Cb = (size_t)b*9*PLANE + off + p;
#pragma unroll
    for (int co = 0; co < 3; co++) {
        float v = g_curv[Vb + (size_t)co*PLANE];
#pragma unroll
        for (int t = 0; t < 9; t++)
            v += wc[((size_t)co*65 + 64)*9 + t] * dnb[t];
        g_csk[Cb + (size_t)(6+co)*PLANE] = 0.1f + 0.9f/(1.f + expf(-v));
    }
}

// ---------------- one propagation step ----------------
__global__ void prop_kernel(const float* __restrict__ Din, float* __restrict__ Dout,
                            int off, int Hs, int Ws) {
    int NPs = Hs*Ws;
    int gid = blockIdx.x*blockDim.x + threadIdx.x;
    if (gid >= BATCH*NPs) return;
    int b = gid / NPs, p = gid % NPs;
    int y = p / Ws, x = p % Ws;
    const float* Db = Din + (size_t)b*NPs;
    float d = Db[p];
    size_t Ab = (size_t)b*24*PLANE + off + p;
    size_t Cb = (size_t)b*9*PLANE + off + p;
    const int offy[8] = {-1,-1,-1, 0, 0, 1, 1, 1};
    const int offx[8] = {-1, 0, 1,-1, 1,-1, 0, 1};
    const int dil[3]  = {1, 2, 4};
    float mix = 0.f;
#pragma unroll
    for (int k = 0; k < 3; k++) {
        float agg = g_csk[Cb + (size_t)k*PLANE] * d;
        int dd = dil[k];
#pragma unroll
        for (int j = 0; j < 8; j++) {
            int ny = y + offy[j]*dd, nx = x + offx[j]*dd;
            float nb = (ny >= 0 && ny < Hs && nx >= 0 && nx < Ws) ? Db[(size_t)ny*Ws + nx] : 0.f;
            agg += g_A[Ab + (size_t)(k*8+j)*PLANE] * nb;
        }
        float sig = g_csk[Cb + (size_t)(3+k)*PLANE];
        float kap = g_csk[Cb + (size_t)(6+k)*PLANE];
        mix += sig * (d + kap*(agg - d));
    }
    size_t xb = (size_t)b*6*PLANE + off + p;
    float dls = g_x[xb + 3*(size_t)PLANE];
    float mls = g_x[xb + 4*(size_t)PLANE];
    Dout[(size_t)b*NPs + p] = mls*(0.9f*dls + 0.1f*mix) + (1.f - mls)*mix;
}

// ---------------- host orchestration ----------------
extern "C" void kernel_launch(void* const* d_in, const int* in_sizes, int n_in,
                              void* d_out, int out_size) {
    (void)in_sizes; (void)n_in; (void)out_size;
    const float* I  = (const float*)d_in[0];
    const float* DL = (const float*)d_in[1];
    const float* ML = (const float*)d_in[2];
    const float* E  = (const float*)d_in[3];
    const float* w0 = (const float*)d_in[4];
    const float* b0 = (const float*)d_in[5];
    const float* w1 = (const float*)d_in[6];
    const float* b1 = (const float*)d_in[7];
    const float* w2 = (const float*)d_in[8];
    const float* b2 = (const float*)d_in[9];
    const float* wa = (const float*)d_in[10];
    const float* ba = (const float*)d_in[11];
    const float* wg = (const float*)d_in[12];
    const float* bg = (const float*)d_in[13];
    const float* wc = (const float*)d_in[14];
    const float* bc = (const float*)d_in[15];
    float* out = (float*)d_out;

    float *px, *pf0, *pf1, *pD, *pD2, *pDp;
    float *pwT0, *pwT1, *pwT2, *pwTagc, *pbagc;
    cudaGetSymbolAddress((void**)&px,    g_x);
    cudaGetSymbolAddress((void**)&pf0,   g_f0);
    cudaGetSymbolAddress((void**)&pf1,   g_f1);
    cudaGetSymbolAddress((void**)&pD,    g_D);
    cudaGetSymbolAddress((void**)&pD2,   g_D2);
    cudaGetSymbolAddress((void**)&pDp,   g_Dp);
    cudaGetSymbolAddress((void**)&pwT0,  g_wT0);
    cudaGetSymbolAddress((void**)&pwT1,  g_wT1);
    cudaGetSymbolAddress((void**)&pwT2,  g_wT2);
    cudaGetSymbolAddress((void**)&pwTagc, g_wTagc);
    cudaGetSymbolAddress((void**)&pbagc, g_bagc);

    const int SC[3]   = {4, 2, 1};
    const int OFFS[3] = {OFF_S4, OFF_S2, OFF_S1};

    // launch 0: weight prep ; launch 1: s=1 input prep
    prep_weights<<<(95616 + 255)/256, 256>>>(w0, w1, w2, wa, ba, wg, bg, wc, bc);
    {
        int tot = BATCH*H0*W0;
        prep_kernel<1, false><<<(tot+255)/256, 256>>>(I, DL, ML, E, OFF_S1, H0, W0);
    }

    // launches 2-5: s=1 convs (launch index 3 = enc1 64->64 lands in ncu window)
    {
        int Hs = H0, Ws = W0, NPs = Hs*Ws;
        dim3 cb(CTW, 8);
        dim3 cg(Ws/CTW, (Hs + CTH2 - 1)/CTH2, BATCH);
        conv3x3_kernel<64, 0><<<cg, cb>>>(px,  PLANE, OFF_S1, 6,  6,  pwT0, b0, pf0, NPs, 0, Hs, Ws);
        conv3x3_kernel<64, 0><<<cg, cb>>>(pf0, NPs,   0,  64, 64, pwT1, b1, pf1, NPs, 0, Hs, Ws);
        conv3x3_kernel<64, 0><<<cg, cb>>>(pf1, NPs,   0,  64, 64, pwT2, b2, pf0, NPs, 0, Hs, Ws);
        conv3x3_kernel<32, 1><<<cg, cb>>>(pf0, NPs,   0,  64, 64, pwTagc, pbagc, nullptr, 0, OFF_S1, Hs, Ws);
    }

    // remaining prep + s=2, s=4 convs
    {
        int Hs = H0/2, Ws = W0/2, tot = BATCH*Hs*Ws;
        prep_kernel<2, false><<<(tot+255)/256, 256>>>(I, DL, ML, E, OFF_S2, Hs, Ws);
        Hs = H0/4; Ws = W0/4; tot = BATCH*Hs*Ws;
        prep_kernel<4, true><<<(tot+255)/256, 256>>>(I, DL, ML, E, OFF_S4, Hs, Ws);
    }
    for (int si = 1; si >= 0; si--) {
        int S = SC[si];
        int off = OFFS[si];
        int Hs = H0/S, Ws = W0/S, NPs = Hs*Ws;
        dim3 cb(CTW, 8);
        dim3 cg(Ws/CTW, (Hs + CTH2 - 1)/CTH2, BATCH);
        conv3x3_kernel<64, 0><<<cg, cb>>>(px,  PLANE, off, 6,  6,  pwT0, b0, pf0, NPs, 0, Hs, Ws);
        conv3x3_kernel<64, 0><<<cg, cb>>>(pf0, NPs,   0,  64, 64, pwT1, b1, pf1, NPs, 0, Hs, Ws);
        conv3x3_kernel<64, 0><<<cg, cb>>>(pf1, NPs,   0,  64, 64, pwT2, b2, pf0, NPs, 0, Hs, Ws);
        conv3x3_kernel<32, 1><<<cg, cb>>>(pf0, NPs,   0,  64, 64, pwTagc, pbagc, nullptr, 0, off, Hs, Ws);
    }

    // propagation chain: coarse-to-fine
    int Hp = 0, Wp = 0;
    for (int si = 0; si < 3; si++) {
        int S = SC[si];
        int off = OFFS[si];
        int Hs = H0/S, Ws = W0/S, NPs = Hs*Ws;
        int tot = BATCH*NPs, blk = (tot + 255)/256;

        if (si > 0) init_d_kernel<<<blk, 256>>>(off, Hp, Wp, Hs, Ws);
        curvd_kernel<<<blk, 256>>>(wc, off, Hs, Ws);

        float* Dc = pD;
        float* Dn = pD2;
        for (int st = 0; st < 6; st++) {
            prop_kernel<<<blk, 256>>>(Dc, Dn, off, Hs, Ws);
            float* t = Dc; Dc = Dn; Dn = t;
        }
        if (si < 2) {
            cudaMemcpyAsync(pDp, Dc, sizeof(float)*(size_t)BATCH*NPs, cudaMemcpyDeviceToDevice);
        } else {
            cudaMemcpyAsync(out, Dc, sizeof(float)*(size_t)BATCH*NPs, cudaMemcpyDeviceToDevice);
        }
        Hp = Hs; Wp = Ws;
    }
}